// round 3
// baseline (speedup 1.0000x reference)
#include <cuda_runtime.h>
#include <cuda_bf16.h>
#include <math.h>
#include <stdint.h>

// Problem dims
#define B_    512
#define NSLOT 128
#define IN_   2048
#define MEMD  64
#define OUT_  2048
#define NC    130      // fused front-GEMM cols: 64 (q) + 1 (forget_x) + 65 (remember_x)
#define CONC  2176     // IN + 2*MEM

// ---------------- scratch (static __device__, no allocations) ----------------
__device__ float g_Wcat[IN_ * NC];
__device__ float g_T[B_ * NC];
__device__ __align__(256) __nv_bfloat16 g_Ah[B_ * CONC];    // interm hi (bf16)
__device__ __align__(256) __nv_bfloat16 g_Al[B_ * CONC];    // interm lo
__device__ __align__(256) __nv_bfloat16 g_Bh[OUT_ * CONC];  // W_o^T hi [N,K]
__device__ __align__(256) __nv_bfloat16 g_Bl[OUT_ * CONC];  // W_o^T lo

// ---------------- helpers ----------------
__device__ __forceinline__ uint32_t smem_u32(const void* p) {
    uint32_t a;
    asm("{ .reg .u64 t; cvta.to.shared.u64 t, %1; cvt.u32.u64 %0, t; }" : "=r"(a) : "l"(p));
    return a;
}
__device__ __forceinline__ void cp16(uint32_t dst, const void* src) {
    asm volatile("cp.async.cg.shared.global [%0], [%1], 16;" :: "r"(dst), "l"(src) : "memory");
}
#define CP_COMMIT() asm volatile("cp.async.commit_group;" ::: "memory")
#define CP_WAIT(n)  asm volatile("cp.async.wait_group %0;" :: "n"(n) : "memory")

__device__ __forceinline__ void ldsm4(uint32_t& r0, uint32_t& r1, uint32_t& r2, uint32_t& r3, uint32_t addr) {
    asm volatile("ldmatrix.sync.aligned.m8n8.x4.shared.b16 {%0,%1,%2,%3}, [%4];"
        : "=r"(r0), "=r"(r1), "=r"(r2), "=r"(r3) : "r"(addr));
}
#define MMA16816(d, a, b0v, b1v) \
    asm volatile("mma.sync.aligned.m16n8k16.row.col.f32.bf16.bf16.f32 " \
        "{%0,%1,%2,%3}, {%4,%5,%6,%7}, {%8,%9}, {%0,%1,%2,%3};" \
        : "+f"((d)[0]), "+f"((d)[1]), "+f"((d)[2]), "+f"((d)[3]) \
        : "r"((a)[0]), "r"((a)[1]), "r"((a)[2]), "r"((a)[3]), "r"(b0v), "r"(b1v))

// ============================================================================
// Kernel 0: pack Wcat = [W_ar | W_f_top | W_r_top], init T with biases
// ============================================================================
__global__ void pack_init_kernel(const float* __restrict__ W_ar, const float* __restrict__ b_ar,
                                 const float* __restrict__ W_f,  const float* __restrict__ b_f,
                                 const float* __restrict__ W_r,  const float* __restrict__ b_r)
{
    int i = blockIdx.x * blockDim.x + threadIdx.x;
    const int NW = IN_ * NC;
    if (i < NW) {
        int k = i / NC, j = i - k * NC;
        float v;
        if (j < 64)       v = W_ar[k * 64 + j];
        else if (j == 64) v = W_f[k];
        else              v = W_r[k * 65 + (j - 65)];
        g_Wcat[i] = v;
    } else if (i < NW + B_ * NC) {
        int r = i - NW;
        int j = r % NC;
        float v;
        if (j < 64)       v = b_ar[j];
        else if (j == 64) v = b_f[0];
        else              v = b_r[j - 65];
        g_T[r] = v;
    }
}

// ============================================================================
// Kernel 0b: transpose + bf16 hi/lo split of W_o -> g_Bh/g_Bl [N=2048, K=2176]
// ============================================================================
__global__ __launch_bounds__(256) void transpose_split_kernel(const float* __restrict__ Wo)
{
    __shared__ float tile[32][33];
    int n0 = blockIdx.x * 32, k0 = blockIdx.y * 32;
    int tx = threadIdx.x & 31, ty = threadIdx.x >> 5;   // 32 x 8
    #pragma unroll
    for (int dy = 0; dy < 4; dy++) {
        int k = k0 + ty * 4 + dy;
        tile[ty * 4 + dy][tx] = Wo[(size_t)k * OUT_ + n0 + tx];
    }
    __syncthreads();
    #pragma unroll
    for (int dy = 0; dy < 4; dy++) {
        int n = n0 + ty * 4 + dy;
        int k = k0 + tx;
        float v = tile[tx][ty * 4 + dy];
        __nv_bfloat16 h = __float2bfloat16(v);
        g_Bh[(size_t)n * CONC + k] = h;
        g_Bl[(size_t)n * CONC + k] = __float2bfloat16(v - __bfloat162float(h));
    }
}

// ============================================================================
// Kernel 1: front GEMM  T += x[512,2048] @ Wcat[2048,130]   (split-K, atomic)
// ============================================================================
__global__ __launch_bounds__(256) void gemm1_kernel(const float* __restrict__ x)
{
    __shared__ float As[16][68];
    __shared__ float Bs[16][68];
    int t  = threadIdx.x;
    int tx = t & 15, ty = t >> 4;
    int bm0 = blockIdx.x * 64;
    int bn0 = blockIdx.y * 64;
    int k0b = blockIdx.z * 256;

    float acc[4][4] = {};

    for (int kt = 0; kt < 16; kt++) {
        int k0 = k0b + kt * 16;
        {
            int row = t >> 2, kq = t & 3;
            float4 v = *(const float4*)&x[(size_t)(bm0 + row) * IN_ + k0 + kq * 4];
            As[kq * 4 + 0][row] = v.x;
            As[kq * 4 + 1][row] = v.y;
            As[kq * 4 + 2][row] = v.z;
            As[kq * 4 + 3][row] = v.w;
        }
        {
            int kr = t >> 4, cq = t & 15;
            #pragma unroll
            for (int j = 0; j < 4; j++) {
                int col = bn0 + cq * 4 + j;
                Bs[kr][cq * 4 + j] = (col < NC) ? g_Wcat[(size_t)(k0 + kr) * NC + col] : 0.f;
            }
        }
        __syncthreads();
        #pragma unroll
        for (int k = 0; k < 16; k++) {
            float a0 = As[k][ty * 4 + 0], a1 = As[k][ty * 4 + 1];
            float a2 = As[k][ty * 4 + 2], a3 = As[k][ty * 4 + 3];
            float b0 = Bs[k][tx * 4 + 0], b1 = Bs[k][tx * 4 + 1];
            float b2 = Bs[k][tx * 4 + 2], b3 = Bs[k][tx * 4 + 3];
            acc[0][0] += a0 * b0; acc[0][1] += a0 * b1; acc[0][2] += a0 * b2; acc[0][3] += a0 * b3;
            acc[1][0] += a1 * b0; acc[1][1] += a1 * b1; acc[1][2] += a1 * b2; acc[1][3] += a1 * b3;
            acc[2][0] += a2 * b0; acc[2][1] += a2 * b1; acc[2][2] += a2 * b2; acc[2][3] += a2 * b3;
            acc[3][0] += a3 * b0; acc[3][1] += a3 * b1; acc[3][2] += a3 * b2; acc[3][3] += a3 * b3;
        }
        __syncthreads();
    }
    #pragma unroll
    for (int i = 0; i < 4; i++) {
        int row = bm0 + ty * 4 + i;
        #pragma unroll
        for (int j = 0; j < 4; j++) {
            int col = bn0 + tx * 4 + j;
            if (col < NC) atomicAdd(&g_T[(size_t)row * NC + col], acc[i][j]);
        }
    }
}

// ============================================================================
// Kernel 2: per-batch fused attention + softmax + recalls + memory update
// Writes the "interm" row directly as bf16 hi/lo into g_Ah/g_Al.
// ============================================================================
#define FUSED_SMEM_FLOATS (8320 + 4160 + 64*3 + 65 + 128*4 + 8)
#define FUSED_SMEM_BYTES  (FUSED_SMEM_FLOATS * 4)

__global__ __launch_bounds__(256) void fused_mem_kernel(
    const float* __restrict__ x, const float* __restrict__ memory,
    const float* __restrict__ W_pr, const float* __restrict__ b_pr,
    const float* __restrict__ W_f,  const float* __restrict__ W_r,
    float* __restrict__ new_mem)
{
    extern __shared__ float sm[];
    float* mem_s = sm;
    float* wrb_s = sm + 8320;
    float* q_s   = wrb_s + 4160;
    float* wpr_s = q_s + 64;
    float* wfb_s = wpr_s + 64;
    float* rx_s  = wfb_s + 64;
    float* sc_s  = rx_s + 65;
    float* ps_s  = sc_s + 128;
    float* f_s   = ps_s + 128;
    float* g_s   = f_s + 128;
    float* red   = g_s + 128;

    int b = blockIdx.x, t = threadIdx.x;
    const float* mg = memory + (size_t)b * (NSLOT * MEMD);
    size_t abase = (size_t)b * CONC;

    for (int i = t; i < NSLOT * MEMD; i += 256)
        mem_s[(i >> 6) * 65 + (i & 63)] = mg[i];
    for (int i = t; i < 64 * 65; i += 256)
        wrb_s[i] = W_r[IN_ * 65 + i];
    if (t < 64) {
        q_s[t]   = g_T[(size_t)b * NC + t];
        wpr_s[t] = W_pr[t];
        wfb_s[t] = W_f[IN_ + t];
    }
    if (t < 65) rx_s[t] = g_T[(size_t)b * NC + 65 + t];
    if (t == 0) { red[6] = g_T[(size_t)b * NC + 64]; red[7] = b_pr[0]; }

    // x row -> bf16 hi/lo (independent of smem state)
    {
        const float* xr = x + (size_t)b * IN_;
        for (int i = t; i < IN_; i += 256) {
            float v = xr[i];
            __nv_bfloat16 h = __float2bfloat16(v);
            g_Ah[abase + i] = h;
            g_Al[abase + i] = __float2bfloat16(v - __bfloat162float(h));
        }
    }
    __syncthreads();

    if (t < NSLOT) {
        const float* mr = mem_s + t * 65;
        float s = 0.f, p = 0.f, f = 0.f, g = 0.f;
        #pragma unroll 8
        for (int k = 0; k < 64; k++) {
            float mv = mr[k];
            s += mv * q_s[k];
            p += mv * wpr_s[k];
            f += mv * wfb_s[k];
            g += mv * wrb_s[k * 65 + 64];
        }
        sc_s[t] = s;
        ps_s[t] = p + red[7];
        f_s[t]  = 1.1f / (1.f + expf(-(f + red[6])));
        g_s[t]  = g + rx_s[64];
    }
    __syncthreads();

    if (t < 32) {
        float m1 = -1e30f, m2 = -1e30f;
        for (int i = t; i < 128; i += 32) { m1 = fmaxf(m1, sc_s[i]); m2 = fmaxf(m2, ps_s[i]); }
        #pragma unroll
        for (int o = 16; o; o >>= 1) {
            m1 = fmaxf(m1, __shfl_xor_sync(0xffffffffu, m1, o));
            m2 = fmaxf(m2, __shfl_xor_sync(0xffffffffu, m2, o));
        }
        if (t == 0) { red[0] = m1; red[1] = m2; }
    }
    __syncthreads();
    if (t < 128) { sc_s[t] = expf(sc_s[t] - red[0]); ps_s[t] = expf(ps_s[t] - red[1]); }
    __syncthreads();
    if (t < 32) {
        float s1 = 0.f, s2 = 0.f;
        for (int i = t; i < 128; i += 32) { s1 += sc_s[i]; s2 += ps_s[i]; }
        #pragma unroll
        for (int o = 16; o; o >>= 1) {
            s1 += __shfl_xor_sync(0xffffffffu, s1, o);
            s2 += __shfl_xor_sync(0xffffffffu, s2, o);
        }
        if (t == 0) { red[2] = 1.f / s1; red[3] = 1.f / s2; }
    }
    __syncthreads();

    if (t < 64) {
        float a = 0.f, pv = 0.f;
        #pragma unroll 8
        for (int n = 0; n < 128; n++) {
            float mv = mem_s[n * 65 + t];
            a  += mv * sc_s[n];
            pv += mv * ps_s[n];
        }
        a *= red[2]; pv *= red[3];
        __nv_bfloat16 ah = __float2bfloat16(a);
        g_Ah[abase + IN_ + t] = ah;
        g_Al[abase + IN_ + t] = __float2bfloat16(a - __bfloat162float(ah));
        __nv_bfloat16 ph = __float2bfloat16(pv);
        g_Ah[abase + IN_ + 64 + t] = ph;
        g_Al[abase + IN_ + 64 + t] = __float2bfloat16(pv - __bfloat162float(ph));
    }

    // memory update
    for (int tile = t; tile < 512; tile += 256) {
        int n0 = (tile >> 4) * 4;
        int m0 = (tile & 15) * 4;
        float acc[4][4] = {};
        const float* mp = mem_s + n0 * 65;
        #pragma unroll 8
        for (int k = 0; k < 64; k++) {
            float a0 = mp[k], a1 = mp[65 + k], a2 = mp[130 + k], a3 = mp[195 + k];
            const float* wp = wrb_s + k * 65 + m0;
            float b0 = wp[0], b1 = wp[1], b2 = wp[2], b3 = wp[3];
            acc[0][0] += a0 * b0; acc[0][1] += a0 * b1; acc[0][2] += a0 * b2; acc[0][3] += a0 * b3;
            acc[1][0] += a1 * b0; acc[1][1] += a1 * b1; acc[1][2] += a1 * b2; acc[1][3] += a1 * b3;
            acc[2][0] += a2 * b0; acc[2][1] += a2 * b1; acc[2][2] += a2 * b2; acc[2][3] += a2 * b3;
            acc[3][0] += a3 * b0; acc[3][1] += a3 * b1; acc[3][2] += a3 * b2; acc[3][3] += a3 * b3;
        }
        #pragma unroll
        for (int i = 0; i < 4; i++) {
            int n = n0 + i;
            float fg = f_s[n], gg = g_s[n];
            const float* mr = mem_s + n * 65;
            float4 o;
            o.x = mr[m0 + 0] * fg + gg * (rx_s[m0 + 0] + acc[i][0]);
            o.y = mr[m0 + 1] * fg + gg * (rx_s[m0 + 1] + acc[i][1]);
            o.z = mr[m0 + 2] * fg + gg * (rx_s[m0 + 2] + acc[i][2]);
            o.w = mr[m0 + 3] * fg + gg * (rx_s[m0 + 3] + acc[i][3]);
            *(float4*)&new_mem[(size_t)b * (NSLOT * MEMD) + n * MEMD + m0] = o;
        }
    }
}

// ============================================================================
// Kernel 3: output GEMM via mma.sync bf16 (hi/lo split, fp32 accum)
// BM=128, BN=128, BK=32, grid (4,16)=64 CTAs, 256 threads (8 warps: 4M x 2N).
// SMEM: 2 stages x {Ah,Al,Bh,Bl} x (128 rows x 80B) = 81,920 B.
// ============================================================================
#define GKT      (CONC / 32)          // 68 k-tiles
#define PITCH_B  80                   // bytes per smem row (64 data + 16 pad)
#define TILE_B   (128 * PITCH_B)      // 10240
#define STAGE_B  (4 * TILE_B)         // 40960
#define GO_SMEM  (2 * STAGE_B)        // 81920

__global__ __launch_bounds__(256) void gemm_out_mma_kernel(
    const float* __restrict__ bias, float* __restrict__ C)
{
    extern __shared__ char smem[];
    uint32_t sb = smem_u32(smem);
    int t = threadIdx.x;
    int wid = t >> 5, lane = t & 31;
    int bm0 = blockIdx.x * 128;
    int bn0 = blockIdx.y * 128;

    // ---- per-thread load mapping: 8 chunks of 16B per k-tile stage ----
    const __nv_bfloat16* gp[8];
    uint32_t sp[8];
    {
        const __nv_bfloat16* tb[4] = {
            g_Ah + (size_t)bm0 * CONC, g_Al + (size_t)bm0 * CONC,
            g_Bh + (size_t)bn0 * CONC, g_Bl + (size_t)bn0 * CONC };
        #pragma unroll
        for (int j = 0; j < 8; j++) {
            int idx = t + j * 256;          // 0..2047
            int tile = idx >> 9;            // 512 chunks per tile
            int wc = idx & 511;
            int r = wc >> 2, c = wc & 3;
            gp[j] = tb[tile] + (size_t)r * CONC + c * 8;
            sp[j] = (uint32_t)(tile * TILE_B + r * PITCH_B + c * 16);
        }
    }

    // ---- warp tile mapping: wm in 0..3 (32 rows), wn in 0..1 (64 cols) ----
    int wm = wid & 3, wn = wid >> 2;
    uint32_t aoff[2], boff[4];
    {
        int lr = lane & 15, lc = (lane >> 4) * 16;
        #pragma unroll
        for (int a = 0; a < 2; a++)
            aoff[a] = (uint32_t)((wm * 32 + a * 16 + lr) * PITCH_B + lc);
        #pragma unroll
        for (int g = 0; g < 4; g++)
            boff[g] = (uint32_t)((wn * 64 + g * 16 + lr) * PITCH_B + lc);
    }

    float acc[2][8][4];
    #pragma unroll
    for (int a = 0; a < 2; a++)
        #pragma unroll
        for (int b = 0; b < 8; b++)
            #pragma unroll
            for (int i = 0; i < 4; i++) acc[a][b][i] = 0.f;

    // ---- prologue: stage 0 = k-tile 0 ----
    #pragma unroll
    for (int j = 0; j < 8; j++) cp16(sb + sp[j], gp[j]);
    CP_COMMIT();

    for (int kt = 0; kt < GKT; kt++) {
        if (kt + 1 < GKT) {
            uint32_t stb = sb + ((kt + 1) & 1) * STAGE_B;
            const int ko = (kt + 1) * 32;
            #pragma unroll
            for (int j = 0; j < 8; j++) cp16(stb + sp[j], gp[j] + ko);
            CP_COMMIT();
            CP_WAIT(1);
        } else {
            CP_WAIT(0);
        }
        __syncthreads();

        uint32_t stb = sb + (kt & 1) * STAGE_B;
        uint32_t sA_h = stb, sA_l = stb + TILE_B, sB_h = stb + 2 * TILE_B, sB_l = stb + 3 * TILE_B;

        #pragma unroll
        for (int ks = 0; ks < 2; ks++) {
            uint32_t kb = ks * 32;
            uint32_t ah[2][4], al[2][4], bb[4][4];
            #pragma unroll
            for (int a = 0; a < 2; a++) {
                ldsm4(ah[a][0], ah[a][1], ah[a][2], ah[a][3], sA_h + aoff[a] + kb);
                ldsm4(al[a][0], al[a][1], al[a][2], al[a][3], sA_l + aoff[a] + kb);
            }
            #pragma unroll
            for (int g = 0; g < 4; g++)
                ldsm4(bb[g][0], bb[g][1], bb[g][2], bb[g][3], sB_h + boff[g] + kb);
            #pragma unroll
            for (int a = 0; a < 2; a++)
                #pragma unroll
                for (int g = 0; g < 4; g++) {
                    MMA16816(acc[a][2 * g + 0], ah[a], bb[g][0], bb[g][2]);
                    MMA16816(acc[a][2 * g + 1], ah[a], bb[g][1], bb[g][3]);
                }
            #pragma unroll
            for (int a = 0; a < 2; a++)
                #pragma unroll
                for (int g = 0; g < 4; g++) {
                    MMA16816(acc[a][2 * g + 0], al[a], bb[g][0], bb[g][2]);
                    MMA16816(acc[a][2 * g + 1], al[a], bb[g][1], bb[g][3]);
                }
            // reload B regs with Bl, do Ah*Bl
            #pragma unroll
            for (int g = 0; g < 4; g++)
                ldsm4(bb[g][0], bb[g][1], bb[g][2], bb[g][3], sB_l + boff[g] + kb);
            #pragma unroll
            for (int a = 0; a < 2; a++)
                #pragma unroll
                for (int g = 0; g < 4; g++) {
                    MMA16816(acc[a][2 * g + 0], ah[a], bb[g][0], bb[g][2]);
                    MMA16816(acc[a][2 * g + 1], ah[a], bb[g][1], bb[g][3]);
                }
        }
        __syncthreads();
    }

    // ---- epilogue: add bias, store ----
    int lr = lane >> 2, lc2 = (lane & 3) * 2;
    #pragma unroll
    for (int a = 0; a < 2; a++) {
        int row = bm0 + wm * 32 + a * 16 + lr;
        #pragma unroll
        for (int b = 0; b < 8; b++) {
            int col = bn0 + wn * 64 + b * 8 + lc2;
            float b0 = bias[col], b1 = bias[col + 1];
            float2 v0 = make_float2(acc[a][b][0] + b0, acc[a][b][1] + b1);
            float2 v1 = make_float2(acc[a][b][2] + b0, acc[a][b][3] + b1);
            *(float2*)&C[(size_t)row * OUT_ + col] = v0;
            *(float2*)&C[(size_t)(row + 8) * OUT_ + col] = v1;
        }
    }
}

// ============================================================================
extern "C" void kernel_launch(void* const* d_in, const int* in_sizes, int n_in,
                              void* d_out, int out_size)
{
    const float* x      = (const float*)d_in[0];
    const float* memory = (const float*)d_in[1];
    const float* W_ar   = (const float*)d_in[2];
    const float* b_ar   = (const float*)d_in[3];
    const float* W_pr   = (const float*)d_in[4];
    const float* b_pr   = (const float*)d_in[5];
    const float* W_f    = (const float*)d_in[6];
    const float* b_f    = (const float*)d_in[7];
    const float* W_r    = (const float*)d_in[8];
    const float* b_r    = (const float*)d_in[9];
    const float* W_o    = (const float*)d_in[10];
    const float* b_o    = (const float*)d_in[11];

    float* out     = (float*)d_out;
    float* new_mem = out + (size_t)B_ * OUT_;

    cudaFuncSetAttribute(fused_mem_kernel,
                         cudaFuncAttributeMaxDynamicSharedMemorySize, FUSED_SMEM_BYTES);
    cudaFuncSetAttribute(gemm_out_mma_kernel,
                         cudaFuncAttributeMaxDynamicSharedMemorySize, GO_SMEM);

    // 0: pack weights + bias-init T
    {
        int total = IN_ * NC + B_ * NC;
        pack_init_kernel<<<(total + 255) / 256, 256>>>(W_ar, b_ar, W_f, b_f, W_r, b_r);
    }
    // 0b: W_o -> transposed bf16 hi/lo
    {
        dim3 g(OUT_ / 32, CONC / 32);
        transpose_split_kernel<<<g, 256>>>(W_o);
    }
    // 1: front GEMM
    {
        dim3 g(8, 3, 8);
        gemm1_kernel<<<g, 256>>>(x);
    }
    // 2: fused attention + recalls + memory update (emits A hi/lo)
    fused_mem_kernel<<<B_, 256, FUSED_SMEM_BYTES>>>(x, memory, W_pr, b_pr, W_f, W_r, new_mem);
    // 3: output GEMM on tensor cores (mma.sync fallback path)
    {
        dim3 g(B_ / 128, OUT_ / 128);
        gemm_out_mma_kernel<<<g, 256, GO_SMEM>>>(b_o, out);
    }
}

// round 5
// speedup vs baseline: 1.3650x; 1.3650x over previous
#include <cuda_runtime.h>
#include <cuda_bf16.h>
#include <math.h>
#include <stdint.h>

// Problem dims
#define B_    512
#define NSLOT 128
#define IN_   2048
#define MEMD  64
#define OUT_  2048
#define NC    130      // fused front-GEMM cols: 64 (q) + 1 (forget_x) + 65 (remember_x)
#define CONC  2176     // IN + 2*MEM

// ---------------- scratch (static __device__, no allocations) ----------------
__device__ float g_Wcat[IN_ * NC];
__device__ float g_T[B_ * NC];
__device__ __align__(256) __nv_bfloat16 g_Ah[B_ * CONC];    // interm hi (bf16)
__device__ __align__(256) __nv_bfloat16 g_Al[B_ * CONC];    // interm lo
__device__ __align__(256) __nv_bfloat16 g_Bh[OUT_ * CONC];  // W_o^T hi [N,K]
__device__ __align__(256) __nv_bfloat16 g_Bl[OUT_ * CONC];  // W_o^T lo
__device__ __align__(256) float g_Cp[2 * B_ * OUT_];        // split-K partials

// ---------------- helpers ----------------
typedef unsigned long long u64t;
__device__ __forceinline__ u64t pk2(float lo, float hi) {
    u64t r; asm("mov.b64 %0, {%1,%2};" : "=l"(r) : "f"(lo), "f"(hi)); return r;
}
__device__ __forceinline__ void fma2(u64t& d, u64t a, u64t b) {
    asm("fma.rn.f32x2 %0, %1, %2, %3;" : "=l"(d) : "l"(a), "l"(b), "l"(d));
}
__device__ __forceinline__ float2 upk2(u64t v) {
    float lo, hi; asm("mov.b64 {%0,%1}, %2;" : "=f"(lo), "=f"(hi) : "l"(v));
    return make_float2(lo, hi);
}
__device__ __forceinline__ uint32_t smem_u32(const void* p) {
    uint32_t a;
    asm("{ .reg .u64 t; cvta.to.shared.u64 t, %1; cvt.u32.u64 %0, t; }" : "=r"(a) : "l"(p));
    return a;
}
__device__ __forceinline__ void cp16(uint32_t dst, const void* src) {
    asm volatile("cp.async.cg.shared.global [%0], [%1], 16;" :: "r"(dst), "l"(src) : "memory");
}
#define CP_COMMIT() asm volatile("cp.async.commit_group;" ::: "memory")
#define CP_WAIT(n)  asm volatile("cp.async.wait_group %0;" :: "n"(n) : "memory")

__device__ __forceinline__ void ldsm4(uint32_t& r0, uint32_t& r1, uint32_t& r2, uint32_t& r3, uint32_t addr) {
    asm volatile("ldmatrix.sync.aligned.m8n8.x4.shared.b16 {%0,%1,%2,%3}, [%4];"
        : "=r"(r0), "=r"(r1), "=r"(r2), "=r"(r3) : "r"(addr));
}
#define MMA16816(d, a, b0v, b1v) \
    asm volatile("mma.sync.aligned.m16n8k16.row.col.f32.bf16.bf16.f32 " \
        "{%0,%1,%2,%3}, {%4,%5,%6,%7}, {%8,%9}, {%0,%1,%2,%3};" \
        : "+f"((d)[0]), "+f"((d)[1]), "+f"((d)[2]), "+f"((d)[3]) \
        : "r"((a)[0]), "r"((a)[1]), "r"((a)[2]), "r"((a)[3]), "r"(b0v), "r"(b1v))

// ============================================================================
// Kernel 0: pack Wcat = [W_ar | W_f_top | W_r_top], init T with biases
// ============================================================================
__global__ void pack_init_kernel(const float* __restrict__ W_ar, const float* __restrict__ b_ar,
                                 const float* __restrict__ W_f,  const float* __restrict__ b_f,
                                 const float* __restrict__ W_r,  const float* __restrict__ b_r)
{
    int i = blockIdx.x * blockDim.x + threadIdx.x;
    const int NW = IN_ * NC;
    if (i < NW) {
        int k = i / NC, j = i - k * NC;
        float v;
        if (j < 64)       v = W_ar[k * 64 + j];
        else if (j == 64) v = W_f[k];
        else              v = W_r[k * 65 + (j - 65)];
        g_Wcat[i] = v;
    } else if (i < NW + B_ * NC) {
        int r = i - NW;
        int j = r % NC;
        float v;
        if (j < 64)       v = b_ar[j];
        else if (j == 64) v = b_f[0];
        else              v = b_r[j - 65];
        g_T[r] = v;
    }
}

// ============================================================================
// Kernel 0b: transpose + bf16 hi/lo split of W_o -> g_Bh/g_Bl [N=2048, K=2176]
// ============================================================================
__global__ __launch_bounds__(256) void transpose_split_kernel(const float* __restrict__ Wo)
{
    __shared__ float tile[32][33];
    int n0 = blockIdx.x * 32, k0 = blockIdx.y * 32;
    int tx = threadIdx.x & 31, ty = threadIdx.x >> 5;   // 32 x 8
    #pragma unroll
    for (int dy = 0; dy < 4; dy++) {
        int k = k0 + ty * 4 + dy;
        tile[ty * 4 + dy][tx] = Wo[(size_t)k * OUT_ + n0 + tx];
    }
    __syncthreads();
    #pragma unroll
    for (int dy = 0; dy < 4; dy++) {
        int n = n0 + ty * 4 + dy;
        int k = k0 + tx;
        float v = tile[tx][ty * 4 + dy];
        __nv_bfloat16 h = __float2bfloat16(v);
        g_Bh[(size_t)n * CONC + k] = h;
        g_Bl[(size_t)n * CONC + k] = __float2bfloat16(v - __bfloat162float(h));
    }
}

// ============================================================================
// Kernel 1: front GEMM  T += x[512,2048] @ Wcat[2048,130]   (split-K, atomic)
// ============================================================================
__global__ __launch_bounds__(256) void gemm1_kernel(const float* __restrict__ x)
{
    __shared__ float As[16][68];
    __shared__ float Bs[16][68];
    int t  = threadIdx.x;
    int tx = t & 15, ty = t >> 4;
    int bm0 = blockIdx.x * 64;
    int bn0 = blockIdx.y * 64;
    int k0b = blockIdx.z * 256;

    float acc[4][4] = {};

    for (int kt = 0; kt < 16; kt++) {
        int k0 = k0b + kt * 16;
        {
            int row = t >> 2, kq = t & 3;
            float4 v = *(const float4*)&x[(size_t)(bm0 + row) * IN_ + k0 + kq * 4];
            As[kq * 4 + 0][row] = v.x;
            As[kq * 4 + 1][row] = v.y;
            As[kq * 4 + 2][row] = v.z;
            As[kq * 4 + 3][row] = v.w;
        }
        {
            int kr = t >> 4, cq = t & 15;
            #pragma unroll
            for (int j = 0; j < 4; j++) {
                int col = bn0 + cq * 4 + j;
                Bs[kr][cq * 4 + j] = (col < NC) ? g_Wcat[(size_t)(k0 + kr) * NC + col] : 0.f;
            }
        }
        __syncthreads();
        #pragma unroll
        for (int k = 0; k < 16; k++) {
            float a0 = As[k][ty * 4 + 0], a1 = As[k][ty * 4 + 1];
            float a2 = As[k][ty * 4 + 2], a3 = As[k][ty * 4 + 3];
            float b0 = Bs[k][tx * 4 + 0], b1 = Bs[k][tx * 4 + 1];
            float b2 = Bs[k][tx * 4 + 2], b3 = Bs[k][tx * 4 + 3];
            acc[0][0] += a0 * b0; acc[0][1] += a0 * b1; acc[0][2] += a0 * b2; acc[0][3] += a0 * b3;
            acc[1][0] += a1 * b0; acc[1][1] += a1 * b1; acc[1][2] += a1 * b2; acc[1][3] += a1 * b3;
            acc[2][0] += a2 * b0; acc[2][1] += a2 * b1; acc[2][2] += a2 * b2; acc[2][3] += a2 * b3;
            acc[3][0] += a3 * b0; acc[3][1] += a3 * b1; acc[3][2] += a3 * b2; acc[3][3] += a3 * b3;
        }
        __syncthreads();
    }
    #pragma unroll
    for (int i = 0; i < 4; i++) {
        int row = bm0 + ty * 4 + i;
        #pragma unroll
        for (int j = 0; j < 4; j++) {
            int col = bn0 + tx * 4 + j;
            if (col < NC) atomicAdd(&g_T[(size_t)row * NC + col], acc[i][j]);
        }
    }
}

// ============================================================================
// Kernel 2: per-batch fused attention + softmax + recalls + memory update
// pitch-66 smem rows; f32x2 packed FMA in the update GEMM.
// ============================================================================
#define PIT   66
#define FUSED_SMEM_FLOATS (128*PIT + 64*PIT + 64*3 + 66 + 128*4 + 8)
#define FUSED_SMEM_BYTES  (FUSED_SMEM_FLOATS * 4)

__global__ __launch_bounds__(256, 4) void fused_mem_kernel(
    const float* __restrict__ x, const float* __restrict__ memory,
    const float* __restrict__ W_pr, const float* __restrict__ b_pr,
    const float* __restrict__ W_f,  const float* __restrict__ W_r,
    float* __restrict__ new_mem)
{
    extern __shared__ float sm[];
    float* mem_s = sm;                        // [128][66]
    float* wrb_s = sm + 128 * PIT;            // [64][66]
    float* q_s   = wrb_s + 64 * PIT;          // 64
    float* wpr_s = q_s + 64;                  // 64
    float* wfb_s = wpr_s + 64;                // 64
    float* rx_s  = wfb_s + 64;                // 66 (65 used)
    float* sc_s  = rx_s + 66;                 // 128
    float* ps_s  = sc_s + 128;                // 128
    float* f_s   = ps_s + 128;                // 128
    float* g_s   = f_s + 128;                 // 128
    float* red   = g_s + 128;                 // 8

    int b = blockIdx.x, t = threadIdx.x;
    const float* mg = memory + (size_t)b * (NSLOT * MEMD);
    size_t abase = (size_t)b * CONC;

    for (int i = t; i < NSLOT * MEMD; i += 256)
        mem_s[(i >> 6) * PIT + (i & 63)] = mg[i];
    for (int i = t; i < 64 * 65; i += 256) {
        int r = i / 65, c = i - r * 65;
        wrb_s[r * PIT + c] = W_r[IN_ * 65 + i];
    }
    if (t < 64) {
        q_s[t]   = g_T[(size_t)b * NC + t];
        wpr_s[t] = W_pr[t];
        wfb_s[t] = W_f[IN_ + t];
    }
    if (t < 65) rx_s[t] = g_T[(size_t)b * NC + 65 + t];
    if (t == 0) { red[6] = g_T[(size_t)b * NC + 64]; red[7] = b_pr[0]; }

    // x row -> bf16 hi/lo (independent of smem state)
    {
        const float* xr = x + (size_t)b * IN_;
        for (int i = t; i < IN_; i += 256) {
            float v = xr[i];
            __nv_bfloat16 h = __float2bfloat16(v);
            g_Ah[abase + i] = h;
            g_Al[abase + i] = __float2bfloat16(v - __bfloat162float(h));
        }
    }
    __syncthreads();

    if (t < NSLOT) {
        const float* mr = mem_s + t * PIT;
        float s = 0.f, p = 0.f, f = 0.f, g = 0.f;
        #pragma unroll 8
        for (int k = 0; k < 64; k++) {
            float mv = mr[k];
            s += mv * q_s[k];
            p += mv * wpr_s[k];
            f += mv * wfb_s[k];
            g += mv * wrb_s[k * PIT + 64];
        }
        sc_s[t] = s;
        ps_s[t] = p + red[7];
        f_s[t]  = 1.1f / (1.f + expf(-(f + red[6])));
        g_s[t]  = g + rx_s[64];
    }
    __syncthreads();

    if (t < 32) {
        float m1 = -1e30f, m2 = -1e30f;
        for (int i = t; i < 128; i += 32) { m1 = fmaxf(m1, sc_s[i]); m2 = fmaxf(m2, ps_s[i]); }
        #pragma unroll
        for (int o = 16; o; o >>= 1) {
            m1 = fmaxf(m1, __shfl_xor_sync(0xffffffffu, m1, o));
            m2 = fmaxf(m2, __shfl_xor_sync(0xffffffffu, m2, o));
        }
        if (t == 0) { red[0] = m1; red[1] = m2; }
    }
    __syncthreads();
    if (t < 128) { sc_s[t] = expf(sc_s[t] - red[0]); ps_s[t] = expf(ps_s[t] - red[1]); }
    __syncthreads();
    if (t < 32) {
        float s1 = 0.f, s2 = 0.f;
        for (int i = t; i < 128; i += 32) { s1 += sc_s[i]; s2 += ps_s[i]; }
        #pragma unroll
        for (int o = 16; o; o >>= 1) {
            s1 += __shfl_xor_sync(0xffffffffu, s1, o);
            s2 += __shfl_xor_sync(0xffffffffu, s2, o);
        }
        if (t == 0) { red[2] = 1.f / s1; red[3] = 1.f / s2; }
    }
    __syncthreads();

    if (t < 64) {
        float a = 0.f, pv = 0.f;
        #pragma unroll 8
        for (int n = 0; n < 128; n++) {
            float mv = mem_s[n * PIT + t];
            a  += mv * sc_s[n];
            pv += mv * ps_s[n];
        }
        a *= red[2]; pv *= red[3];
        __nv_bfloat16 ah = __float2bfloat16(a);
        g_Ah[abase + IN_ + t] = ah;
        g_Al[abase + IN_ + t] = __float2bfloat16(a - __bfloat162float(ah));
        __nv_bfloat16 ph = __float2bfloat16(pv);
        g_Ah[abase + IN_ + 64 + t] = ph;
        g_Al[abase + IN_ + 64 + t] = __float2bfloat16(pv - __bfloat162float(ph));
    }

    // memory update: new_mem = mem*forget + gate * (rx + mem @ Wr_bot)
    // f32x2 packed FMA, 4x4 micro-tiles (pairs packed along m)
    for (int tile = t; tile < 512; tile += 256) {
        int n0 = (tile >> 4) * 4;
        int m0 = (tile & 15) * 4;
        u64t acc2[4][2] = {{0ull, 0ull}, {0ull, 0ull}, {0ull, 0ull}, {0ull, 0ull}};
        const float* mp = mem_s + n0 * PIT;
        const float* wb = wrb_s + m0;
        #pragma unroll 8
        for (int k = 0; k < 64; k++) {
            float2 b01 = *(const float2*)&wb[k * PIT];
            float2 b23 = *(const float2*)&wb[k * PIT + 2];
            u64t bp0 = pk2(b01.x, b01.y);
            u64t bp1 = pk2(b23.x, b23.y);
            #pragma unroll
            for (int i = 0; i < 4; i++) {
                u64t ap = pk2(mp[i * PIT + k], mp[i * PIT + k]);
                fma2(acc2[i][0], ap, bp0);
                fma2(acc2[i][1], ap, bp1);
            }
        }
        #pragma unroll
        for (int i = 0; i < 4; i++) {
            int n = n0 + i;
            float fg = f_s[n], gg = g_s[n];
            const float* mr = mem_s + n * PIT;
            float2 v0 = upk2(acc2[i][0]);
            float2 v1 = upk2(acc2[i][1]);
            float4 o;
            o.x = mr[m0 + 0] * fg + gg * (rx_s[m0 + 0] + v0.x);
            o.y = mr[m0 + 1] * fg + gg * (rx_s[m0 + 1] + v0.y);
            o.z = mr[m0 + 2] * fg + gg * (rx_s[m0 + 2] + v1.x);
            o.w = mr[m0 + 3] * fg + gg * (rx_s[m0 + 3] + v1.y);
            *(float4*)&new_mem[(size_t)b * (NSLOT * MEMD) + n * MEMD + m0] = o;
        }
    }
}

// ============================================================================
// Kernel 3: output GEMM via mma.sync bf16 (hi/lo split, fp32 accum), split-K=2
// BM=128, BN=128, BK=32, grid (4,16,2)=128 CTAs, 256 threads (8 warps: 4M x 2N)
// Each kz half accumulates 34 k-tiles into g_Cp[kz]; reduce kernel adds bias.
// ============================================================================
#define GKT_H    (CONC / 32 / 2)      // 34 k-tiles per half
#define PITCH_B  80
#define TILE_B   (128 * PITCH_B)      // 10240
#define STAGE_B  (4 * TILE_B)         // 40960
#define GO_SMEM  (2 * STAGE_B)        // 81920

__global__ __launch_bounds__(256) void gemm_out_mma_kernel()
{
    extern __shared__ char smem[];
    uint32_t sb = smem_u32(smem);
    int t = threadIdx.x;
    int wid = t >> 5, lane = t & 31;
    int bm0 = blockIdx.x * 128;
    int bn0 = blockIdx.y * 128;
    int kz  = blockIdx.z;
    const int KB0 = kz * GKT_H * 32;   // element offset of this half's K range

    // ---- per-thread load mapping: 8 chunks of 16B per k-tile stage ----
    const __nv_bfloat16* gp[8];
    uint32_t sp[8];
    {
        const __nv_bfloat16* tb[4] = {
            g_Ah + (size_t)bm0 * CONC + KB0, g_Al + (size_t)bm0 * CONC + KB0,
            g_Bh + (size_t)bn0 * CONC + KB0, g_Bl + (size_t)bn0 * CONC + KB0 };
        #pragma unroll
        for (int j = 0; j < 8; j++) {
            int idx = t + j * 256;
            int tile = idx >> 9;
            int wc = idx & 511;
            int r = wc >> 2, c = wc & 3;
            gp[j] = tb[tile] + (size_t)r * CONC + c * 8;
            sp[j] = (uint32_t)(tile * TILE_B + r * PITCH_B + c * 16);
        }
    }

    // ---- warp tile mapping: wm 0..3 (32 rows), wn 0..1 (64 cols) ----
    int wm = wid & 3, wn = wid >> 2;
    uint32_t aoff[2], boff[4];
    {
        int lr = lane & 15, lc = (lane >> 4) * 16;
        #pragma unroll
        for (int a = 0; a < 2; a++)
            aoff[a] = (uint32_t)((wm * 32 + a * 16 + lr) * PITCH_B + lc);
        #pragma unroll
        for (int g = 0; g < 4; g++)
            boff[g] = (uint32_t)((wn * 64 + g * 16 + lr) * PITCH_B + lc);
    }

    float acc[2][8][4];
    #pragma unroll
    for (int a = 0; a < 2; a++)
        #pragma unroll
        for (int b = 0; b < 8; b++)
            #pragma unroll
            for (int i = 0; i < 4; i++) acc[a][b][i] = 0.f;

    // ---- prologue ----
    #pragma unroll
    for (int j = 0; j < 8; j++) cp16(sb + sp[j], gp[j]);
    CP_COMMIT();

    for (int kt = 0; kt < GKT_H; kt++) {
        if (kt + 1 < GKT_H) {
            uint32_t stb = sb + ((kt + 1) & 1) * STAGE_B;
            const int ko = (kt + 1) * 32;
            #pragma unroll
            for (int j = 0; j < 8; j++) cp16(stb + sp[j], gp[j] + ko);
            CP_COMMIT();
            CP_WAIT(1);
        } else {
            CP_WAIT(0);
        }
        __syncthreads();

        uint32_t stb = sb + (kt & 1) * STAGE_B;
        uint32_t sA_h = stb, sA_l = stb + TILE_B, sB_h = stb + 2 * TILE_B, sB_l = stb + 3 * TILE_B;

        #pragma unroll
        for (int ks = 0; ks < 2; ks++) {
            uint32_t kb = ks * 32;
            uint32_t ah[2][4], al[2][4], bh[4][4], bl[4][4];
            #pragma unroll
            for (int a = 0; a < 2; a++) {
                ldsm4(ah[a][0], ah[a][1], ah[a][2], ah[a][3], sA_h + aoff[a] + kb);
                ldsm4(al[a][0], al[a][1], al[a][2], al[a][3], sA_l + aoff[a] + kb);
            }
            #pragma unroll
            for (int g = 0; g < 4; g++) {
                ldsm4(bh[g][0], bh[g][1], bh[g][2], bh[g][3], sB_h + boff[g] + kb);
                ldsm4(bl[g][0], bl[g][1], bl[g][2], bl[g][3], sB_l + boff[g] + kb);
            }
            #pragma unroll
            for (int a = 0; a < 2; a++)
                #pragma unroll
                for (int g = 0; g < 4; g++) {
                    MMA16816(acc[a][2 * g + 0], ah[a], bh[g][0], bh[g][2]);
                    MMA16816(acc[a][2 * g + 1], ah[a], bh[g][1], bh[g][3]);
                }
            #pragma unroll
            for (int a = 0; a < 2; a++)
                #pragma unroll
                for (int g = 0; g < 4; g++) {
                    MMA16816(acc[a][2 * g + 0], al[a], bh[g][0], bh[g][2]);
                    MMA16816(acc[a][2 * g + 1], al[a], bh[g][1], bh[g][3]);
                }
            #pragma unroll
            for (int a = 0; a < 2; a++)
                #pragma unroll
                for (int g = 0; g < 4; g++) {
                    MMA16816(acc[a][2 * g + 0], ah[a], bl[g][0], bl[g][2]);
                    MMA16816(acc[a][2 * g + 1], ah[a], bl[g][1], bl[g][3]);
                }
        }
        __syncthreads();
    }

    // ---- epilogue: store partial (no bias) ----
    float* P = g_Cp + (size_t)kz * (B_ * OUT_);
    int lr = lane >> 2, lc2 = (lane & 3) * 2;
    #pragma unroll
    for (int a = 0; a < 2; a++) {
        int row = bm0 + wm * 32 + a * 16 + lr;
        #pragma unroll
        for (int b = 0; b < 8; b++) {
            int col = bn0 + wn * 64 + b * 8 + lc2;
            *(float2*)&P[(size_t)row * OUT_ + col] = make_float2(acc[a][b][0], acc[a][b][1]);
            *(float2*)&P[(size_t)(row + 8) * OUT_ + col] = make_float2(acc[a][b][2], acc[a][b][3]);
        }
    }
}

// ============================================================================
// Kernel 4: reduce partials + bias -> out
// ============================================================================
__global__ __launch_bounds__(256) void reduce_bias_kernel(const float* __restrict__ bias,
                                                          float* __restrict__ out)
{
    int i = (blockIdx.x * 256 + threadIdx.x) * 4;
    float4 p0 = *(const float4*)&g_Cp[i];
    float4 p1 = *(const float4*)&g_Cp[B_ * OUT_ + i];
    int col = i & (OUT_ - 1);
    float4 bb = *(const float4*)&bias[col];
    float4 o;
    o.x = p0.x + p1.x + bb.x;
    o.y = p0.y + p1.y + bb.y;
    o.z = p0.z + p1.z + bb.z;
    o.w = p0.w + p1.w + bb.w;
    *(float4*)&out[i] = o;
}

// ============================================================================
extern "C" void kernel_launch(void* const* d_in, const int* in_sizes, int n_in,
                              void* d_out, int out_size)
{
    const float* x      = (const float*)d_in[0];
    const float* memory = (const float*)d_in[1];
    const float* W_ar   = (const float*)d_in[2];
    const float* b_ar   = (const float*)d_in[3];
    const float* W_pr   = (const float*)d_in[4];
    const float* b_pr   = (const float*)d_in[5];
    const float* W_f    = (const float*)d_in[6];
    const float* b_f    = (const float*)d_in[7];
    const float* W_r    = (const float*)d_in[8];
    const float* b_r    = (const float*)d_in[9];
    const float* W_o    = (const float*)d_in[10];
    const float* b_o    = (const float*)d_in[11];

    float* out     = (float*)d_out;
    float* new_mem = out + (size_t)B_ * OUT_;

    cudaFuncSetAttribute(fused_mem_kernel,
                         cudaFuncAttributeMaxDynamicSharedMemorySize, FUSED_SMEM_BYTES);
    cudaFuncSetAttribute(gemm_out_mma_kernel,
                         cudaFuncAttributeMaxDynamicSharedMemorySize, GO_SMEM);

    // 0: pack weights + bias-init T
    {
        int total = IN_ * NC + B_ * NC;
        pack_init_kernel<<<(total + 255) / 256, 256>>>(W_ar, b_ar, W_f, b_f, W_r, b_r);
    }
    // 0b: W_o -> transposed bf16 hi/lo
    {
        dim3 g(OUT_ / 32, CONC / 32);
        transpose_split_kernel<<<g, 256>>>(W_o);
    }
    // 1: front GEMM
    {
        dim3 g(8, 3, 8);
        gemm1_kernel<<<g, 256>>>(x);
    }
    // 2: fused attention + recalls + memory update (emits A hi/lo)
    fused_mem_kernel<<<B_, 256, FUSED_SMEM_BYTES>>>(x, memory, W_pr, b_pr, W_f, W_r, new_mem);
    // 3: output GEMM on tensor cores, split-K=2
    {
        dim3 g(B_ / 128, OUT_ / 128, 2);
        gemm_out_mma_kernel<<<g, 256, GO_SMEM>>>();
    }
    // 4: reduce + bias
    reduce_bias_kernel<<<(B_ * OUT_) / 1024, 256>>>(b_o, out);
}